// round 3
// baseline (speedup 1.0000x reference)
#include <cuda_runtime.h>

// ---------------------------------------------------------------------------
// Fused Goal_Conditioned_Policies forward: one CTA per sample (B = 4096).
// Banded pipeline: conv1/conv2 processed in 4 bands of 4 conv2-output rows so
// shared memory fits 2 CTAs/SM (occupancy fix vs round 1).
// conv1(3->32,s2) -> relu -> conv2(32->64,s2) -> relu -> meanpool -> MLP -> softmax
// ---------------------------------------------------------------------------

#define B_SAMPLES 4096
#define NVAR      50
#define NTHREADS  256

// conv2 weights pre-transposed to [ic][oc][12] (9 used + 3 pad) for aligned
// float4 loads. Rebuilt deterministically every launch.
__device__ __align__(16) float g_w2t[32 * 64 * 12];

__global__ void w2t_prep_kernel(const float* __restrict__ w2) {
    int i = blockIdx.x * blockDim.x + threadIdx.x;   // over 32*64 = 2048
    if (i < 2048) {
        int ic = i >> 6, oc = i & 63;
        float* dst = &g_w2t[ic * 768 + oc * 12];
        const float* src = &w2[(oc * 32 + ic) * 9];
        #pragma unroll
        for (int k = 0; k < 9; k++) dst[k] = src[k];
        dst[9] = dst[10] = dst[11] = 0.f;
    }
}

// ---- shared memory layout (floats) ----
#define XB_OFF   0                      // x band [3][19][67]
#define XB_SZ    (3 * 19 * 67)          // 3819
#define H1B_OFF  (XB_OFF + XB_SZ)       // h1 band [32][9][35]
#define H1B_SZ   (32 * 9 * 35)          // 10080
#define CS_OFF   (H1B_OFF + H1B_SZ)     // C[b] 50x50
#define CS_SZ    2500
#define WS1_OFF  (CS_OFF + CS_SZ)       // conv1 weights 32*3*9
#define WS1_SZ   864
#define B1_OFF   (WS1_OFF + WS1_SZ)
#define B2_OFF   (B1_OFF + 32)
#define POOL_OFF (B2_OFF + 64)
#define X1_OFF   (POOL_OFF + 64)
#define X2_OFF   (X1_OFF + 128)
#define E_OFF    (X2_OFF + 64)
#define X3_OFF   (E_OFF + 64)
#define X5_OFF   (X3_OFF + 128)
#define X6_OFF   (X5_OFF + 64)
#define X7_OFF   (X6_OFF + 64)
#define LG_OFF   (X7_OFF + 64)
#define RED_OFF  (LG_OFF + 64)
#define SMEM_FLOATS (RED_OFF + 4)
#define SMEM_BYTES  (SMEM_FLOATS * 4)   // ~72.3 KB -> 2 CTAs/SM

__global__ __launch_bounds__(NTHREADS, 2)
void gcp_fused_kernel(const float* __restrict__ x,    const float* __restrict__ C,
                      const float* __restrict__ w1,   const float* __restrict__ b1,
                      const float* __restrict__ b2,
                      const float* __restrict__ encw, const float* __restrict__ encb,
                      const float* __restrict__ f1w,  const float* __restrict__ f1b,
                      const float* __restrict__ f2w,  const float* __restrict__ f2b,
                      const float* __restrict__ f3w,  const float* __restrict__ f3b,
                      const float* __restrict__ f4w,  const float* __restrict__ f4b,
                      const float* __restrict__ f5w,  const float* __restrict__ f5b,
                      const float* __restrict__ ow,   const float* __restrict__ ob,
                      float* __restrict__ out)
{
    extern __shared__ float sm[];
    const int b    = blockIdx.x;
    const int tid  = threadIdx.x;
    const int wrp  = tid >> 5;
    const int lane = tid & 31;

    // ---- one-time init: zero band buffers (pads must stay 0), stage C/w1/biases ----
    for (int i = tid; i < XB_SZ + H1B_SZ; i += NTHREADS) sm[i] = 0.f;
    for (int i = tid; i < WS1_SZ; i += NTHREADS) sm[WS1_OFF + i] = w1[i];
    if (tid < 32) sm[B1_OFF + tid] = b1[tid];
    if (tid < 64) sm[B2_OFF + tid] = b2[tid];
    for (int i = tid; i < CS_SZ; i += NTHREADS) sm[CS_OFF + i] = C[b * 2500 + i];

    const float* xb = x + (size_t)b * (3 * 64 * 64);

    const int halfq = lane >> 4;   // conv2: which of 2 row-groups in half-warp
    const int cx    = lane & 15;   // conv2 output column
    const int oc2b  = wrp * 8;     // conv2: 8 output channels per warp
    const int oc1b  = wrp * 4;     // conv1: 4 output channels per warp

    float pool_acc[8];
    #pragma unroll
    for (int o = 0; o < 8; o++) pool_acc[o] = 0.f;

    // =====================================================================
    // 4 bands; band t covers conv2 output rows [4t, 4t+4)
    //   needs h1 rows r1 in [8t-1, 8t+7] (9 rows, local j = r1-(8t-1))
    //   needs x  rows xr in [16t-3, 16t+15] (19 rows, local i = xr-(16t-3))
    // =====================================================================
    for (int t = 0; t < 4; t++) {
        __syncthreads();   // prior band's conv2 reads done; buffers writable

        // ---- load x band (zero rows outside [0,64)) ----
        for (int i = tid; i < 3 * 19 * 64; i += NTHREADS) {
            int ic  = i / (19 * 64);
            int rem = i - ic * (19 * 64);
            int r   = rem >> 6;
            int c   = rem & 63;
            int xr  = 16 * t - 3 + r;
            float v = (xr >= 0 && xr < 64) ? xb[ic * 4096 + xr * 64 + c] : 0.f;
            int cp  = c + 1;
            sm[XB_OFF + ic * (19 * 67) + r * 67 + (cp ^ ((cp >> 5) & 1))] = v;
        }
        __syncthreads();

        // ---- conv1 band: h1 rows j=0..8, warp owns 4 oc, lane = col ----
        {
            float a1[9][4];
            #pragma unroll
            for (int j = 0; j < 9; j++)
                #pragma unroll
                for (int o = 0; o < 4; o++) a1[j][o] = sm[B1_OFF + oc1b + o];

            #pragma unroll
            for (int ic = 0; ic < 3; ic++) {
                float wr1[4][9];
                #pragma unroll
                for (int o = 0; o < 4; o++)
                    #pragma unroll
                    for (int k = 0; k < 9; k++)
                        wr1[o][k] = sm[WS1_OFF + (oc1b + o) * 27 + ic * 9 + k];

                const float* xc = &sm[XB_OFF + ic * (19 * 67)];
                #pragma unroll
                for (int j = 0; j < 9; j++) {
                    #pragma unroll
                    for (int ky = 0; ky < 3; ky++) {
                        const float* row = xc + (2 * j + ky) * 67;
                        #pragma unroll
                        for (int kx = 0; kx < 3; kx++) {
                            int cp = 2 * lane + kx;
                            float v = row[cp ^ ((cp >> 5) & 1)];
                            #pragma unroll
                            for (int o = 0; o < 4; o++)
                                a1[j][o] = fmaf(v, wr1[o][3 * ky + kx], a1[j][o]);
                        }
                    }
                }
            }
            #pragma unroll
            for (int j = 0; j < 9; j++) {
                int r1 = 8 * t - 1 + j;
                bool valid = (unsigned)r1 < 32u;
                int flip = (j >> 1) & 1;
                #pragma unroll
                for (int o = 0; o < 4; o++)
                    sm[H1B_OFF + (oc1b + o) * 315 + j * 35 + ((1 + lane) ^ flip)]
                        = valid ? fmaxf(a1[j][o], 0.f) : 0.f;
            }
        }
        __syncthreads();

        // ---- conv2 band: 64 positions (4 rows x 16 cols), warp owns 8 oc ----
        // lane position p: out row q = halfq + 2p, col cx. h1 local row j = 2q+ky.
        {
            float a2[8][2];
            #pragma unroll
            for (int o = 0; o < 8; o++) {
                float bb = sm[B2_OFF + oc2b + o];
                a2[o][0] = bb; a2[o][1] = bb;
            }

            #pragma unroll 1
            for (int ic = 0; ic < 32; ic++) {
                const float4* wp = (const float4*)(g_w2t + ic * 768 + oc2b * 12);
                float wr[8][9];
                #pragma unroll
                for (int o = 0; o < 8; o++) {
                    float4 u0 = wp[o * 3 + 0];
                    float4 u1 = wp[o * 3 + 1];
                    float4 u2 = wp[o * 3 + 2];
                    wr[o][0] = u0.x; wr[o][1] = u0.y; wr[o][2] = u0.z;
                    wr[o][3] = u0.w; wr[o][4] = u1.x; wr[o][5] = u1.y;
                    wr[o][6] = u1.z; wr[o][7] = u1.w; wr[o][8] = u2.x;
                }
                const float* hc = &sm[H1B_OFF + ic * 315];
                #pragma unroll
                for (int p = 0; p < 2; p++) {
                    const int q = halfq + 2 * p;
                    #pragma unroll
                    for (int ky = 0; ky < 3; ky++) {
                        const int j = 2 * q + ky;
                        const int flip = (j >> 1) & 1;
                        const float* row = hc + j * 35;
                        const int cb = 2 * cx;
                        float t0 = row[(cb + 0) ^ flip];
                        float t1 = row[(cb + 1) ^ flip];
                        float t2 = row[(cb + 2) ^ flip];
                        #pragma unroll
                        for (int o = 0; o < 8; o++) {
                            a2[o][p] = fmaf(t0, wr[o][3 * ky + 0], a2[o][p]);
                            a2[o][p] = fmaf(t1, wr[o][3 * ky + 1], a2[o][p]);
                            a2[o][p] = fmaf(t2, wr[o][3 * ky + 2], a2[o][p]);
                        }
                    }
                }
            }
            #pragma unroll
            for (int o = 0; o < 8; o++)
                pool_acc[o] += fmaxf(a2[o][0], 0.f) + fmaxf(a2[o][1], 0.f);
        }
    }
    __syncthreads();

    // ---- pool: reduce each warp's 8 oc across lanes ----
    #pragma unroll
    for (int o = 0; o < 8; o++) {
        float s = pool_acc[o];
        #pragma unroll
        for (int off = 16; off > 0; off >>= 1)
            s += __shfl_xor_sync(0xffffffffu, s, off);
        if (lane == 0) sm[POOL_OFF + oc2b + o] = s * (1.f / 256.f);
    }
    __syncthreads();

    // =====================================================================
    // MLP head
    // =====================================================================
    if (tid < 128) {
        float s = encb[tid];
        #pragma unroll
        for (int k = 0; k < 64; k++) s = fmaf(sm[POOL_OFF + k], __ldg(&encw[k * 128 + tid]), s);
        sm[X1_OFF + tid] = fmaxf(s, 0.f);
    }
    __syncthreads();
    if (tid < NVAR) {
        float s = f1b[tid];
        #pragma unroll
        for (int k = 0; k < 128; k++) s = fmaf(sm[X1_OFF + k], __ldg(&f1w[k * NVAR + tid]), s);
        sm[X2_OFF + tid] = fmaxf(s, 0.f);
    }
    __syncthreads();
    if (tid < NVAR) {
        float s = 0.f;
        #pragma unroll
        for (int k = 0; k < NVAR; k++) s = fmaf(sm[CS_OFF + tid * NVAR + k], sm[X2_OFF + k], s);
        sm[E_OFF + tid] = s;
    }
    __syncthreads();
    if (tid < 128) {
        float s = f2b[tid];
        #pragma unroll
        for (int k = 0; k < NVAR; k++) s = fmaf(sm[E_OFF + k], __ldg(&f2w[k * 128 + tid]), s);
        sm[X3_OFF + tid] = fmaxf(s, 0.f);
    }
    __syncthreads();
    if (tid < 64) {
        float s = f3b[tid];
        #pragma unroll
        for (int k = 0; k < 128; k++) s = fmaf(sm[X1_OFF + k], __ldg(&f3w[k * 64 + tid]), s);
        #pragma unroll
        for (int k = 0; k < 128; k++) s = fmaf(sm[X3_OFF + k], __ldg(&f3w[(128 + k) * 64 + tid]), s);
        sm[X5_OFF + tid] = fmaxf(s, 0.f);
    }
    __syncthreads();
    if (tid < 64) {
        float s = f4b[tid];
        #pragma unroll
        for (int k = 0; k < 64; k++) s = fmaf(sm[X5_OFF + k], __ldg(&f4w[k * 64 + tid]), s);
        sm[X6_OFF + tid] = fmaxf(s, 0.f);
    }
    __syncthreads();
    if (tid < 64) {
        float s = f5b[tid];
        #pragma unroll
        for (int k = 0; k < 64; k++) s = fmaf(sm[X6_OFF + k], __ldg(&f5w[k * 64 + tid]), s);
        sm[X7_OFF + tid] = fmaxf(s, 0.f);
    }
    __syncthreads();
    if (tid < NVAR) {
        float s = ob[tid];
        #pragma unroll
        for (int k = 0; k < 64; k++) s = fmaf(sm[X7_OFF + k], __ldg(&ow[k * NVAR + tid]), s);
        sm[LG_OFF + tid] = fmaxf(s, 0.f);
    }
    __syncthreads();
    if (tid == 0) {
        float m = sm[LG_OFF];
        for (int i = 1; i < NVAR; i++) m = fmaxf(m, sm[LG_OFF + i]);
        sm[RED_OFF] = m;
    }
    __syncthreads();
    if (tid < NVAR) sm[LG_OFF + tid] = expf(sm[LG_OFF + tid] - sm[RED_OFF]);
    __syncthreads();
    if (tid == 0) {
        float s = 0.f;
        for (int i = 0; i < NVAR; i++) s += sm[LG_OFF + i];
        sm[RED_OFF + 1] = 1.f / s;
    }
    __syncthreads();
    if (tid < NVAR) out[b * NVAR + tid] = sm[LG_OFF + tid] * sm[RED_OFF + 1];
}

extern "C" void kernel_launch(void* const* d_in, const int* in_sizes, int n_in,
                              void* d_out, int out_size)
{
    (void)in_sizes; (void)n_in; (void)out_size;
    const float* x    = (const float*)d_in[0];
    const float* C    = (const float*)d_in[1];
    const float* w1   = (const float*)d_in[2];
    const float* b1   = (const float*)d_in[3];
    const float* w2   = (const float*)d_in[4];
    const float* b2   = (const float*)d_in[5];
    const float* encw = (const float*)d_in[6];
    const float* encb = (const float*)d_in[7];
    const float* f1w  = (const float*)d_in[8];
    const float* f1b  = (const float*)d_in[9];
    const float* f2w  = (const float*)d_in[10];
    const float* f2b  = (const float*)d_in[11];
    const float* f3w  = (const float*)d_in[12];
    const float* f3b  = (const float*)d_in[13];
    const float* f4w  = (const float*)d_in[14];
    const float* f4b  = (const float*)d_in[15];
    const float* f5w  = (const float*)d_in[16];
    const float* f5b  = (const float*)d_in[17];
    const float* ow   = (const float*)d_in[18];
    const float* ob   = (const float*)d_in[19];
    float* out = (float*)d_out;

    w2t_prep_kernel<<<8, 256>>>(w2);

    cudaFuncSetAttribute(gcp_fused_kernel,
                         cudaFuncAttributeMaxDynamicSharedMemorySize, SMEM_BYTES);

    gcp_fused_kernel<<<B_SAMPLES, NTHREADS, SMEM_BYTES>>>(
        x, C, w1, b1, b2, encw, encb, f1w, f1b, f2w, f2b,
        f3w, f3b, f4w, f4b, f5w, f5b, ow, ob, out);
}

// round 5
// speedup vs baseline: 1.9740x; 1.9740x over previous
#include <cuda_runtime.h>
#include <cuda_bf16.h>
#include <cstdint>

// ===========================================================================
// Fused Goal_Conditioned_Policies forward, warp-MMA (HMMA bf16) conv2.
// One CTA per sample (B=4096), 256 threads, 1 CTA/SM (~192 KB smem).
//   conv1 (FFMA fp32, lane=oc, weights in regs) -> P: parity-split NHWC bf16
//   conv2 = GEMM D[256 pos][64 oc] = im2col(P) @ w2^T via mma.sync m16n8k16
//     5 K-chunks of 64 (tap pairs); acc in registers (bias-initialized);
//     relu+meanpool directly from fragments.
//   MLP (fp32 FFMA) -> softmax
// ===========================================================================

#define NTHREADS 256
#define NVAR     50

// ---- smem byte offsets ----
#define P_OFF    0u            // parity NHWC h1: [2][2][4 icg][17][17][16 B] = 73,984
#define XP_OFF   73984u        // x padded fp32 [3][66][68] = 53,856
#define A_OFF    73984u        // A chunk [256 rows][144 B] = 36,864 (aliases XP)
#define B2W_OFF  127840u       // B weights [320 k][144 B] = 46,080
#define CS_OFF   173920u       // C[b] 50x50 fp32 = 10,000
#define W1S_OFF  183920u       // conv1 weights 864 fp32 = 3,456
#define VEC_OFF  187376u       // small vectors (floats below)
#define SMEM_BYTES 192560u

// vec float indices
#define V_B2S  0
#define V_PP   64        // pool partials [8 warps][64]
#define V_POOL 576
#define V_X1   640
#define V_X2   768
#define V_E    832
#define V_X3   896
#define V_X5   1024
#define V_X6   1088
#define V_X7   1152
#define V_LG   1216
#define V_RED  1280

__device__ __forceinline__ uint32_t smem_u32(const void* p) {
    uint32_t a;
    asm("{ .reg .u64 t; cvta.to.shared.u64 t, %1; cvt.u32.u64 %0, t; }" : "=r"(a) : "l"(p));
    return a;
}
__device__ __forceinline__ void ldsm_x4(uint32_t* r, uint32_t addr) {
    asm volatile("ldmatrix.sync.aligned.m8n8.x4.shared.b16 {%0,%1,%2,%3}, [%4];"
        : "=r"(r[0]), "=r"(r[1]), "=r"(r[2]), "=r"(r[3]) : "r"(addr));
}
__device__ __forceinline__ void ldsm_x4_t(uint32_t* r, uint32_t addr) {
    asm volatile("ldmatrix.sync.aligned.m8n8.x4.trans.shared.b16 {%0,%1,%2,%3}, [%4];"
        : "=r"(r[0]), "=r"(r[1]), "=r"(r[2]), "=r"(r[3]) : "r"(addr));
}
__device__ __forceinline__ void mma16816(float* d, const uint32_t* a, const uint32_t* b) {
    asm volatile(
        "mma.sync.aligned.m16n8k16.row.col.f32.bf16.bf16.f32 "
        "{%0,%1,%2,%3}, {%4,%5,%6,%7}, {%8,%9}, {%0,%1,%2,%3};"
        : "+f"(d[0]), "+f"(d[1]), "+f"(d[2]), "+f"(d[3])
        : "r"(a[0]), "r"(a[1]), "r"(a[2]), "r"(a[3]), "r"(b[0]), "r"(b[1]));
}

// B weights bf16, k-major [kk][oc], row padded to 144 B. kk = c*64 + parity*32 + ic.
__device__ __align__(16) __nv_bfloat16 g_B2[320 * 72];

__global__ void b_prep_kernel(const float* __restrict__ w2) {
    int i = blockIdx.x * blockDim.x + threadIdx.x;   // 320*64 = 20480
    if (i >= 320 * 64) return;
    int kk = i >> 6, oc = i & 63;
    int c = kk >> 6, rem = kk & 63;
    int tap = 2 * c + (rem >> 5);
    int ic  = rem & 31;
    float v = (tap < 9) ? w2[(oc * 32 + ic) * 9 + tap] : 0.f;
    g_B2[kk * 72 + oc] = __float2bfloat16(v);
}

__global__ __launch_bounds__(NTHREADS, 1)
void gcp_tc_kernel(const float* __restrict__ x,    const float* __restrict__ C,
                   const float* __restrict__ w1,   const float* __restrict__ b1,
                   const float* __restrict__ b2,
                   const float* __restrict__ encw, const float* __restrict__ encb,
                   const float* __restrict__ f1w,  const float* __restrict__ f1b,
                   const float* __restrict__ f2w,  const float* __restrict__ f2b,
                   const float* __restrict__ f3w,  const float* __restrict__ f3b,
                   const float* __restrict__ f4w,  const float* __restrict__ f4b,
                   const float* __restrict__ f5w,  const float* __restrict__ f5b,
                   const float* __restrict__ ow,   const float* __restrict__ ob,
                   float* __restrict__ out)
{
    extern __shared__ char smc[];
    const uint32_t smaddr = smem_u32(smc);
    const int b    = blockIdx.x;
    const int tid  = threadIdx.x;
    const int wrp  = tid >> 5;
    const int lane = tid & 31;
    float* vec = (float*)(smc + VEC_OFF);

    // ---- stage: zero P+XP (pads must be 0), load B weights, w1, b2, C ----
    {
        uint4 z = make_uint4(0, 0, 0, 0);
        for (int i = tid; i < 7990; i += NTHREADS)      // (P + XP) / 16
            ((uint4*)(smc + P_OFF))[i] = z;
        const uint4* gb = (const uint4*)g_B2;
        for (int i = tid; i < 2880; i += NTHREADS)      // 46080/16
            ((uint4*)(smc + B2W_OFF))[i] = gb[i];
        float* w1s = (float*)(smc + W1S_OFF);
        for (int i = tid; i < 864; i += NTHREADS) w1s[i] = w1[i];
        if (tid < 64) vec[V_B2S + tid] = b2[tid];
        float* cs = (float*)(smc + CS_OFF);
        for (int i = tid; i < 2500; i += NTHREADS) cs[i] = C[b * 2500 + i];
    }
    __syncthreads();

    // ---- x interior into padded [3][66][68] fp32 ----
    {
        float* xp = (float*)(smc + XP_OFF);
        const float4* xg = (const float4*)(x + (size_t)b * 12288);
        for (int i = tid; i < 3072; i += NTHREADS) {
            int ic  = i >> 10;
            int rem = i & 1023;
            int row = rem >> 4;
            int c4  = rem & 15;
            float4 v = xg[i];
            float* d = xp + (ic * 66 + row + 1) * 68 + c4 * 4 + 1;
            d[0] = v.x; d[1] = v.y; d[2] = v.z; d[3] = v.w;
        }
    }
    __syncthreads();

    // =====================================================================
    // conv1: lane = oc (0..31), weights in registers, 2x2 output quads.
    // Writes P parity-split NHWC bf16: [py][px][g=ic/8][17][17][8 ic * bf16]
    // =====================================================================
    {
        float wreg[27];
        {
            const float* w1s = (const float*)(smc + W1S_OFF);
            #pragma unroll
            for (int j = 0; j < 27; j++) wreg[j] = w1s[lane * 27 + j];
        }
        const float breg = b1[lane];
        const float* xp = (const float*)(smc + XP_OFF);

        for (int q = wrp; q < 256; q += 8) {
            int Y = q >> 4, X = q & 15;
            float a00 = breg, a01 = breg, a10 = breg, a11 = breg;
            #pragma unroll
            for (int ic = 0; ic < 3; ic++) {
                const float* base = xp + (ic * 66 + 4 * Y) * 68 + 4 * X;
                float xv[5][5];
                #pragma unroll
                for (int i = 0; i < 5; i++) {
                    float4 v = *(const float4*)(base + i * 68);
                    xv[i][0] = v.x; xv[i][1] = v.y; xv[i][2] = v.z; xv[i][3] = v.w;
                    xv[i][4] = base[i * 68 + 4];
                }
                #pragma unroll
                for (int ky = 0; ky < 3; ky++)
                    #pragma unroll
                    for (int kx = 0; kx < 3; kx++) {
                        float w = wreg[ic * 9 + ky * 3 + kx];
                        a00 = fmaf(xv[ky][kx],         w, a00);
                        a01 = fmaf(xv[ky][2 + kx],     w, a01);
                        a10 = fmaf(xv[2 + ky][kx],     w, a10);
                        a11 = fmaf(xv[2 + ky][2 + kx], w, a11);
                    }
            }
            const int g  = lane >> 3;
            const int lo = (lane & 7) * 2;
            #pragma unroll
            for (int a = 0; a < 2; a++)
                #pragma unroll
                for (int bb = 0; bb < 2; bb++) {
                    int y  = 2 * Y + a,  xx = 2 * X + bb;
                    int py = (y + 1) & 1, iy = (y + 1) >> 1;
                    int px = (xx + 1) & 1, ix = (xx + 1) >> 1;
                    float v = (a == 0) ? (bb == 0 ? a00 : a01) : (bb == 0 ? a10 : a11);
                    uint32_t off = P_OFF +
                        (uint32_t)(((((py * 2 + px) * 4 + g) * 17 + iy) * 17) + ix) * 16u + lo;
                    *(__nv_bfloat16*)(smc + off) = __float2bfloat16(fmaxf(v, 0.f));
                }
        }
    }

    // =====================================================================
    // conv2 GEMM: acc[2 m-tiles][8 n-tiles][4], bias-initialized.
    // 5 chunks of K=64 (tap pairs); A chunk rebuilt per chunk (aliases XP).
    // =====================================================================
    float acc[2][8][4];
    {
        const int cB = (lane & 3) * 2;
        #pragma unroll
        for (int j = 0; j < 8; j++) {
            float b0 = vec[V_B2S + j * 8 + cB];
            float b1v = vec[V_B2S + j * 8 + cB + 1];
            #pragma unroll
            for (int i = 0; i < 2; i++) {
                acc[i][j][0] = b0;  acc[i][j][1] = b1v;
                acc[i][j][2] = b0;  acc[i][j][3] = b1v;
            }
        }
    }
    {
        const int r = tid, oy = r >> 4, ox = r & 15;
        char* dst = smc + A_OFF + (uint32_t)r * 144u;
        const int m0 = wrp * 32;
        const uint32_t a_lane_base = smaddr + A_OFF + (uint32_t)(lane & 15) * 144u
                                     + (uint32_t)(lane >> 4) * 16u;
        const uint32_t b_lane_base = smaddr + B2W_OFF + (uint32_t)(lane & 15) * 144u
                                     + (uint32_t)(lane >> 4) * 16u;

        for (int c = 0; c < 5; c++) {
            __syncthreads();   // conv1 done (c=0) / prior chunk reads done
            // ---- build A rows: tap pair (2c, 2c+1) -> 8 x 16B ----
            {
                int tap = 2 * c, ky = tap / 3, kx = tap - 3 * ky;
                const char* sp = smc + P_OFF +
                    (uint32_t)((((ky & 1) * 2 + (kx & 1)) * 4 * 17 + (oy + (ky >> 1))) * 17
                               + (ox + (kx >> 1))) * 16u;
                *(uint4*)(dst +  0) = *(const uint4*)(sp);
                *(uint4*)(dst + 16) = *(const uint4*)(sp + 4624);
                *(uint4*)(dst + 32) = *(const uint4*)(sp + 2 * 4624);
                *(uint4*)(dst + 48) = *(const uint4*)(sp + 3 * 4624);
            }
            if (c < 4) {
                int tap = 2 * c + 1, ky = tap / 3, kx = tap - 3 * ky;
                const char* sp = smc + P_OFF +
                    (uint32_t)((((ky & 1) * 2 + (kx & 1)) * 4 * 17 + (oy + (ky >> 1))) * 17
                               + (ox + (kx >> 1))) * 16u;
                *(uint4*)(dst + 64) = *(const uint4*)(sp);
                *(uint4*)(dst + 80) = *(const uint4*)(sp + 4624);
                *(uint4*)(dst + 96) = *(const uint4*)(sp + 2 * 4624);
                *(uint4*)(dst + 112) = *(const uint4*)(sp + 3 * 4624);
            } else {
                uint4 z = make_uint4(0, 0, 0, 0);
                *(uint4*)(dst + 64) = z; *(uint4*)(dst + 80) = z;
                *(uint4*)(dst + 96) = z; *(uint4*)(dst + 112) = z;
            }
            __syncthreads();

            // ---- 4 k-steps of 16 ----
            #pragma unroll
            for (int ks = 0; ks < 4; ks++) {
                uint32_t af[2][4];
                #pragma unroll
                for (int i = 0; i < 2; i++)
                    ldsm_x4(af[i], a_lane_base + (uint32_t)(m0 + i * 16) * 144u
                                    + (uint32_t)ks * 32u);
                uint32_t bf[4][4];
                #pragma unroll
                for (int p = 0; p < 4; p++)
                    ldsm_x4_t(bf[p], b_lane_base + (uint32_t)(c * 64 + ks * 16) * 144u
                                      + (uint32_t)p * 32u);
                #pragma unroll
                for (int i = 0; i < 2; i++)
                    #pragma unroll
                    for (int j = 0; j < 8; j++)
                        mma16816(acc[i][j], af[i], &bf[j >> 1][(j & 1) * 2]);
            }
        }
    }

    // ---- relu + meanpool from fragments ----
    {
        #pragma unroll
        for (int j = 0; j < 8; j++) {
            float s0 = 0.f, s1 = 0.f;
            #pragma unroll
            for (int i = 0; i < 2; i++) {
                s0 += fmaxf(acc[i][j][0], 0.f) + fmaxf(acc[i][j][2], 0.f);
                s1 += fmaxf(acc[i][j][1], 0.f) + fmaxf(acc[i][j][3], 0.f);
            }
            s0 += __shfl_xor_sync(0xffffffffu, s0, 4);
            s1 += __shfl_xor_sync(0xffffffffu, s1, 4);
            s0 += __shfl_xor_sync(0xffffffffu, s0, 8);
            s1 += __shfl_xor_sync(0xffffffffu, s1, 8);
            s0 += __shfl_xor_sync(0xffffffffu, s0, 16);
            s1 += __shfl_xor_sync(0xffffffffu, s1, 16);
            if (lane < 4) {
                vec[V_PP + wrp * 64 + j * 8 + lane * 2]     = s0;
                vec[V_PP + wrp * 64 + j * 8 + lane * 2 + 1] = s1;
            }
        }
    }
    __syncthreads();
    if (tid < 64) {
        float s = 0.f;
        #pragma unroll
        for (int w = 0; w < 8; w++) s += vec[V_PP + w * 64 + tid];
        vec[V_POOL + tid] = s * (1.f / 256.f);
    }
    __syncthreads();

    // =====================================================================
    // MLP head (fp32)
    // =====================================================================
    if (tid < 128) {
        float s = encb[tid];
        #pragma unroll
        for (int k = 0; k < 64; k++) s = fmaf(vec[V_POOL + k], __ldg(&encw[k * 128 + tid]), s);
        vec[V_X1 + tid] = fmaxf(s, 0.f);
    }
    __syncthreads();
    if (tid < NVAR) {
        float s = f1b[tid];
        #pragma unroll
        for (int k = 0; k < 128; k++) s = fmaf(vec[V_X1 + k], __ldg(&f1w[k * NVAR + tid]), s);
        vec[V_X2 + tid] = fmaxf(s, 0.f);
    }
    __syncthreads();
    if (tid < NVAR) {
        const float* cs = (const float*)(smc + CS_OFF);
        float s = 0.f;
        #pragma unroll
        for (int k = 0; k < NVAR; k++) s = fmaf(cs[tid * NVAR + k], vec[V_X2 + k], s);
        vec[V_E + tid] = s;
    }
    __syncthreads();
    if (tid < 128) {
        float s = f2b[tid];
        #pragma unroll
        for (int k = 0; k < NVAR; k++) s = fmaf(vec[V_E + k], __ldg(&f2w[k * 128 + tid]), s);
        vec[V_X3 + tid] = fmaxf(s, 0.f);
    }
    __syncthreads();
    if (tid < 64) {
        float s = f3b[tid];
        #pragma unroll
        for (int k = 0; k < 128; k++) s = fmaf(vec[V_X1 + k], __ldg(&f3w[k * 64 + tid]), s);
        #pragma unroll
        for (int k = 0; k < 128; k++) s = fmaf(vec[V_X3 + k], __ldg(&f3w[(128 + k) * 64 + tid]), s);
        vec[V_X5 + tid] = fmaxf(s, 0.f);
    }
    __syncthreads();
    if (tid < 64) {
        float s = f4b[tid];
        #pragma unroll
        for (int k = 0; k < 64; k++) s = fmaf(vec[V_X5 + k], __ldg(&f4w[k * 64 + tid]), s);
        vec[V_X6 + tid] = fmaxf(s, 0.f);
    }
    __syncthreads();
    if (tid < 64) {
        float s = f5b[tid];
        #pragma unroll
        for (int k = 0; k < 64; k++) s = fmaf(vec[V_X6 + k], __ldg(&f5w[k * 64 + tid]), s);
        vec[V_X7 + tid] = fmaxf(s, 0.f);
    }
    __syncthreads();
    if (tid < NVAR) {
        float s = ob[tid];
        #pragma unroll
        for (int k = 0; k < 64; k++) s = fmaf(vec[V_X7 + k], __ldg(&ow[k * NVAR + tid]), s);
        vec[V_LG + tid] = fmaxf(s, 0.f);
    }
    __syncthreads();
    if (tid == 0) {
        float m = vec[V_LG];
        for (int i = 1; i < NVAR; i++) m = fmaxf(m, vec[V_LG + i]);
        vec[V_RED] = m;
    }
    __syncthreads();
    if (tid < NVAR) vec[V_LG + tid] = expf(vec[V_LG + tid] - vec[V_RED]);
    __syncthreads();
    if (tid == 0) {
        float s = 0.f;
        for (int i = 0; i < NVAR; i++) s += vec[V_LG + i];
        vec[V_RED + 1] = 1.f / s;
    }
    __syncthreads();
    if (tid < NVAR) out[b * NVAR + tid] = vec[V_LG + tid] * vec[V_RED + 1];
}

extern "C" void kernel_launch(void* const* d_in, const int* in_sizes, int n_in,
                              void* d_out, int out_size)
{
    (void)in_sizes; (void)n_in; (void)out_size;
    const float* x    = (const float*)d_in[0];
    const float* C    = (const float*)d_in[1];
    const float* w1   = (const float*)d_in[2];
    const float* b1   = (const float*)d_in[3];
    const float* w2   = (const float*)d_in[4];
    const float* b2   = (const float*)d_in[5];
    const float* encw = (const float*)d_in[6];
    const float* encb = (const float*)d_in[7];
    const float* f1w  = (const float*)d_in[8];
    const float* f1b  = (const float*)d_in[9];
    const float* f2w  = (const float*)d_in[10];
    const float* f2b  = (const float*)d_in[11];
    const float* f3w  = (const float*)d_in[12];
    const float* f3b  = (const float*)d_in[13];
    const float* f4w  = (const float*)d_in[14];
    const float* f4b  = (const float*)d_in[15];
    const float* f5w  = (const float*)d_in[16];
    const float* f5b  = (const float*)d_in[17];
    const float* ow   = (const float*)d_in[18];
    const float* ob   = (const float*)d_in[19];
    float* out = (float*)d_out;

    b_prep_kernel<<<80, 256>>>(w2);

    cudaFuncSetAttribute(gcp_tc_kernel,
                         cudaFuncAttributeMaxDynamicSharedMemorySize, SMEM_BYTES);

    gcp_tc_kernel<<<4096, NTHREADS, SMEM_BYTES>>>(
        x, C, w1, b1, b2, encw, encb, f1w, f1b, f2w, f2b,
        f3w, f3b, f4w, f4b, f5w, f5b, ow, ob, out);
}